// round 3
// baseline (speedup 1.0000x reference)
#include <cuda_runtime.h>
#include <cuda_fp16.h>
#include <stdint.h>

#define NDU 60000
#define NDI 90000
#define NDOM (NDU + NDI)      /* 150000 */
#define NTU 200000
#define NTI 300000
#define NALL (NTU + NTI)      /* 500000 */
#define NE  2000000
#define DIM 32
#define NQ  8192
#define ALPHA 0.1f
#define BETA  0.9f

/* ---------------- static device scratch (no allocs allowed) ---------------- */
__device__ __align__(16) float  g_A[(size_t)NALL * DIM];     /* 64 MB  f32 accum */
__device__ __align__(16) __half g_X16[(size_t)NALL * DIM];   /* 32 MB  fp16 gather src */
__device__ __align__(16) __half g_A16[(size_t)NALL * DIM];   /* 32 MB  fp16 gather src */
__device__ __align__(16) float  g_light[(size_t)NDOM * DIM]; /* 19 MB */
__device__ __align__(16) float  g_intra[(size_t)NDOM * DIM]; /* 19 MB */
__device__ float   g_invs[4 * (size_t)NALL];  /* 8 MB  per-conv rsqrt(deg) */
__device__ float   g_w[4 * (size_t)NE];       /* 32 MB per-conv edge weights */
__device__ int     g_remap[NALL];             /* node -> light row, or -1 */
__device__ uint8_t g_needA[3 * (size_t)NALL]; /* layer-1 output needed? */
__device__ int     g_f[2];                    /* index-width flags: 1 => int64 */

/* ---------------- prep: degrees + weights for all 4 convs, batched ------- */
__global__ void k_zero(float* p, size_t n) {
    size_t i = (size_t)blockIdx.x * blockDim.x + threadIdx.x;
    if (i < n) p[i] = 0.f;
}
__device__ __forceinline__ const int* dst_ptr(int set, const int* dom, const int* sep) {
    return (set == 0) ? dom + NE : sep + (size_t)(set - 1) * 2 * NE + NE;
}
__device__ __forceinline__ const int* src_ptr(int set, const int* dom, const int* sep) {
    return (set == 0) ? dom : sep + (size_t)(set - 1) * 2 * NE;
}
__global__ void k_deg_all(const int* __restrict__ dom, const int* __restrict__ sep,
                          float* __restrict__ invs) {
    size_t t = (size_t)blockIdx.x * blockDim.x + threadIdx.x;
    if (t >= (size_t)4 * NE) return;
    int set = (int)(t / NE);
    int e   = (int)(t - (size_t)set * NE);
    atomicAdd(&invs[(size_t)set * NALL + dst_ptr(set, dom, sep)[e]], 1.0f);
}
__global__ void k_rsqrt_all(float* d, size_t n) {
    size_t i = (size_t)blockIdx.x * blockDim.x + threadIdx.x;
    if (i < n) d[i] = rsqrtf(fmaxf(d[i], 1.0f));
}
__global__ void k_edgew_all(const int* __restrict__ dom, const int* __restrict__ sep,
                            const float* __restrict__ invs, float* __restrict__ w) {
    size_t t = (size_t)blockIdx.x * blockDim.x + threadIdx.x;
    if (t >= (size_t)4 * NE) return;
    int set = (int)(t / NE);
    int e   = (int)(t - (size_t)set * NE);
    const float* iv = invs + (size_t)set * NALL;
    w[t] = BETA * iv[src_ptr(set, dom, sep)[e]] * iv[dst_ptr(set, dom, sep)[e]];
}

/* ---------------- remap + layer-1 need masks ---------------- */
__global__ void k_remap_clear(int* m, int n) {
    int i = blockIdx.x * blockDim.x + threadIdx.x;
    if (i < n) m[i] = -1;
}
__global__ void k_remap_set(int* m, const int* __restrict__ uid, const int* __restrict__ iid) {
    int i = blockIdx.x * blockDim.x + threadIdx.x;
    if (i < NDU) m[uid[i]] = i;
    else if (i < NDOM) m[NTU + iid[i - NDU]] = i;
}
__global__ void k_mask_clear(uint8_t* m, size_t n) {
    size_t i = (size_t)blockIdx.x * blockDim.x + threadIdx.x;
    if (i < n) m[i] = 0;
}
__global__ void k_mask_build(const int* __restrict__ sep, const int* __restrict__ remap,
                             uint8_t* __restrict__ needA) {
    size_t t = (size_t)blockIdx.x * blockDim.x + threadIdx.x;
    if (t >= (size_t)3 * NE) return;
    int set = (int)(t / NE);
    int e   = (int)(t - (size_t)set * NE);
    const int* s = sep + (size_t)set * 2 * NE;
    const int* d = s + NE;
    if (__ldg(remap + d[e]) >= 0) needA[(size_t)set * NALL + s[e]] = 1;
}

/* ---------------- inits / converts ---------------- */
/* dst = ALPHA * concat(a,b); n8 = total float4 count, na8 = a's float4 count */
__global__ void k_init_split(float4* __restrict__ d, const float4* __restrict__ a,
                             const float4* __restrict__ b, size_t na8, size_t n8) {
    size_t i = (size_t)blockIdx.x * blockDim.x + threadIdx.x;
    if (i >= n8) return;
    float4 v = (i < na8) ? a[i] : b[i - na8];
    d[i] = make_float4(ALPHA * v.x, ALPHA * v.y, ALPHA * v.z, ALPHA * v.w);
}
__device__ __forceinline__ uint2 pack_half4(float4 v) {
    __half2 h0 = __floats2half2_rn(v.x, v.y);
    __half2 h1 = __floats2half2_rn(v.z, v.w);
    uint2 r;
    r.x = *reinterpret_cast<unsigned*>(&h0);
    r.y = *reinterpret_cast<unsigned*>(&h1);
    return r;
}
/* fp16 convert of concat(a,b) */
__global__ void k_cvt_split(uint2* __restrict__ d, const float4* __restrict__ a,
                            const float4* __restrict__ b, size_t na8, size_t n8) {
    size_t i = (size_t)blockIdx.x * blockDim.x + threadIdx.x;
    if (i >= n8) return;
    d[i] = pack_half4((i < na8) ? a[i] : b[i - na8]);
}
/* fp16 convert in place buffer-to-buffer */
__global__ void k_cvt(uint2* __restrict__ d, const float4* __restrict__ s, size_t n8) {
    size_t i = (size_t)blockIdx.x * blockDim.x + threadIdx.x;
    if (i < n8) d[i] = pack_half4(s[i]);
}
/* light[r] = 3*ALPHA * x[row(r)] gathered from aggru/aggri */
__global__ void k_light_init(float4* __restrict__ light, const float4* __restrict__ au,
                             const float4* __restrict__ ai, const int* __restrict__ uid,
                             const int* __restrict__ iid) {
    size_t i = (size_t)blockIdx.x * blockDim.x + threadIdx.x;
    if (i >= (size_t)NDOM * 8) return;
    int r = (int)(i >> 3);
    int c = (int)(i & 7);
    float4 v = (r < NDU) ? au[(size_t)uid[r] * 8 + c] : ai[(size_t)iid[r - NDU] * 8 + c];
    float k = 3.0f * ALPHA;
    light[i] = make_float4(k * v.x, k * v.y, k * v.z, k * v.w);
}

/* ---------------- the scatter: 8 lanes/edge, fp16 gather, f32 vector RED --
   MODE 0: plain (dst row = dst)
   MODE 1: byte-mask needA (dst row = dst)
   MODE 2: remap (dst row = remap[dst], skip if <0)                         */
template <int MODE>
__global__ void k_scatter(const int* __restrict__ src, const int* __restrict__ dst,
                          const float* __restrict__ w, const __half* __restrict__ h16,
                          float* __restrict__ agg, const uint8_t* __restrict__ needA,
                          const int* __restrict__ remap, int nE) {
    size_t t = (size_t)blockIdx.x * blockDim.x + threadIdx.x;
    int e = (int)(t >> 3);
    int lane = (int)(t & 7);
    if (e >= nE) return;
    int d = __ldg(dst + e);
    int drow = d;
    if (MODE == 1) { if (!__ldg(needA + d)) return; }
    if (MODE == 2) { drow = __ldg(remap + d); if (drow < 0) return; }
    int s = __ldg(src + e);
    float ww = __ldg(w + e);
    uint2 raw = *(const uint2*)(h16 + (size_t)s * DIM + lane * 4);
    __half2 ha = *reinterpret_cast<__half2*>(&raw.x);
    __half2 hb = *reinterpret_cast<__half2*>(&raw.y);
    float2 fa = __half22float2(ha);
    float2 fb = __half22float2(hb);
    float* o = agg + (size_t)drow * DIM + lane * 4;
    asm volatile("red.global.add.v4.f32 [%0], {%1,%2,%3,%4};"
                 :: "l"(o), "f"(fa.x * ww), "f"(fa.y * ww),
                    "f"(fb.x * ww), "f"(fb.y * ww) : "memory");
}

/* ---------------- index width detect (both arrays, one launch) ---------- */
__global__ void k_detect2(const int* __restrict__ a, const int* __restrict__ b, int nElems) {
    __shared__ int any;
    const int* p = blockIdx.x ? b : a;
    if (threadIdx.x == 0) any = 0;
    __syncthreads();
    for (int i = threadIdx.x; i < nElems / 2; i += blockDim.x)
        if (p[2 * i + 1] != 0) any = 1;
    __syncthreads();
    if (threadIdx.x == 0) g_f[blockIdx.x] = (any == 0);
}

/* gamma[p] = dot(light_u, light_i)/9 + dot(intra_u, intra_i); one warp/pair */
__global__ void k_gamma(const void* __restrict__ users, const void* __restrict__ items,
                        const float* __restrict__ light, const float* __restrict__ intra,
                        float* __restrict__ out) {
    int p = (blockIdx.x * blockDim.x + threadIdx.x) >> 5;
    int lane = threadIdx.x & 31;
    if (p >= NQ) return;
    long long u  = g_f[0] ? ((const long long*)users)[p] : (long long)((const int*)users)[p];
    long long it = g_f[1] ? ((const long long*)items)[p] : (long long)((const int*)items)[p];
    size_t ur = (size_t)u * DIM + lane;
    size_t ir = ((size_t)NDU + (size_t)it) * DIM + lane;
    float v = light[ur] * light[ir] * (1.0f / 9.0f) + intra[ur] * intra[ir];
#pragma unroll
    for (int o = 16; o; o >>= 1) v += __shfl_xor_sync(0xffffffffu, v, o);
    if (lane == 0) out[p] = v;
}

/* ---------------- host side ---------------- */
static inline unsigned gb(size_t n) { return (unsigned)((n + 255) / 256); }

extern "C" void kernel_launch(void* const* d_in, const int* in_sizes, int n_in,
                              void* d_out, int out_size) {
    const int*   dom   = (const int*)d_in[0];    /* [2, NE] */
    const int*   sep   = (const int*)d_in[1];    /* [3, 2, NE] */
    const float* aggru = (const float*)d_in[2];  /* [NTU, DIM] */
    const float* aggri = (const float*)d_in[3];  /* [NTI, DIM] */
    const float* domu  = (const float*)d_in[4];  /* [NDU, DIM] */
    const float* domi  = (const float*)d_in[5];  /* [NDI, DIM] */
    const int*   uid   = (const int*)d_in[6];    /* [NDU] */
    const int*   iid   = (const int*)d_in[7];    /* [NDI] */
    const void*  users = d_in[8];                /* [NQ] int32 or int64 */
    const void*  items = d_in[9];
    float* out = (float*)d_out;

    float *A, *light, *intra, *invs, *w;
    __half *X16, *A16;
    int *remap;
    uint8_t *needA;
    cudaGetSymbolAddress((void**)&A, g_A);
    cudaGetSymbolAddress((void**)&X16, g_X16);
    cudaGetSymbolAddress((void**)&A16, g_A16);
    cudaGetSymbolAddress((void**)&light, g_light);
    cudaGetSymbolAddress((void**)&intra, g_intra);
    cudaGetSymbolAddress((void**)&invs, g_invs);
    cudaGetSymbolAddress((void**)&w, g_w);
    cudaGetSymbolAddress((void**)&remap, g_remap);
    cudaGetSymbolAddress((void**)&needA, g_needA);

    const size_t nd8 = (size_t)NDOM * 8;   /* float4 count, dom nodes */
    const size_t na8 = (size_t)NALL * 8;   /* float4 count, all nodes */
    const size_t nu8 = (size_t)NDU * 8;
    const size_t ntu8 = (size_t)NTU * 8;

    /* --- one-time prep: detect, remap, degrees/weights for all 4 convs --- */
    k_detect2<<<2, 256>>>((const int*)users, (const int*)items, NQ);
    k_remap_clear<<<gb(NALL), 256>>>(remap, NALL);
    k_remap_set<<<gb(NDOM), 256>>>(remap, uid, iid);
    k_zero<<<gb((size_t)4 * NALL), 256>>>(invs, (size_t)4 * NALL);
    k_deg_all<<<gb((size_t)4 * NE), 256>>>(dom, sep, invs);
    k_rsqrt_all<<<gb((size_t)4 * NALL), 256>>>(invs, (size_t)4 * NALL);
    k_edgew_all<<<gb((size_t)4 * NE), 256>>>(dom, sep, invs, w);
    k_mask_clear<<<gb((size_t)3 * NALL), 256>>>(needA, (size_t)3 * NALL);
    k_mask_build<<<gb((size_t)3 * NE), 256>>>(sep, remap, needA);

    /* --- intra-domain conv (150K nodes), fully dense --- */
    k_cvt_split<<<gb(nd8), 256>>>((uint2*)X16, (const float4*)domu, (const float4*)domi, nu8, nd8);
    k_init_split<<<gb(nd8), 256>>>((float4*)A, (const float4*)domu, (const float4*)domi, nu8, nd8);
    k_scatter<0><<<gb((size_t)NE * 8), 256>>>(dom, dom + NE, w, X16, A, 0, 0, NE);
    k_cvt<<<gb(nd8), 256>>>((uint2*)A16, (const float4*)A, nd8);
    k_init_split<<<gb(nd8), 256>>>((float4*)intra, (const float4*)domu, (const float4*)domi, nu8, nd8);
    k_scatter<0><<<gb((size_t)NE * 8), 256>>>(dom, dom + NE, w, A16, intra, 0, 0, NE);

    /* --- inter-domain: 3 convs; layer-2 REDs straight into light --- */
    k_cvt_split<<<gb(na8), 256>>>((uint2*)X16, (const float4*)aggru, (const float4*)aggri, ntu8, na8);
    k_light_init<<<gb(nd8), 256>>>((float4*)light, (const float4*)aggru, (const float4*)aggri, uid, iid);
    for (int d = 0; d < 3; d++) {
        const int* s = sep + (size_t)d * 2 * NE;
        const int* t = s + NE;
        const float* wd = w + (size_t)(d + 1) * NE;
        const uint8_t* nd = needA + (size_t)d * NALL;
        k_init_split<<<gb(na8), 256>>>((float4*)A, (const float4*)aggru, (const float4*)aggri, ntu8, na8);
        k_scatter<1><<<gb((size_t)NE * 8), 256>>>(s, t, wd, X16, A, nd, 0, NE);
        k_cvt<<<gb(na8), 256>>>((uint2*)A16, (const float4*)A, na8);
        k_scatter<2><<<gb((size_t)NE * 8), 256>>>(s, t, wd, A16, light, 0, remap, NE);
    }

    /* --- final pairwise dots --- */
    k_gamma<<<NQ / 8, 256>>>(users, items, light, intra, out);
}